// round 1
// baseline (speedup 1.0000x reference)
#include <cuda_runtime.h>
#include <math.h>

#define NP 512
#define TT 12

// ---------------- persistent state (device globals; re-initialized every launch) ----
__device__ float g_h[NP*64];
__device__ float g_c[NP*64];
__device__ float g_ctx[NP*64];
__device__ float g_pos[NP*2];
__device__ float g_cur[NP*2];
__device__ float g_A[NP*64];
__device__ float g_B[NP*64];
__device__ float g_M[2*64];
__device__ float g_bc[64];

__device__ __forceinline__ float sigmf(float x){ return 1.0f/(1.0f + expf(-x)); }

// ---------------- init: copy initial state, zero ctx, fold W_sp/b_sp/b1 into M/bc ----
__global__ void k_init(const float* __restrict__ last_pos, const float* __restrict__ obs,
                       const float* __restrict__ h0, const float* __restrict__ c0,
                       const float* __restrict__ W_sp, const float* __restrict__ b_sp,
                       const float* __restrict__ W1, const float* __restrict__ b1)
{
    int idx = blockIdx.x*blockDim.x + threadIdx.x;
    if (idx < NP*64){ g_h[idx]=h0[idx]; g_c[idx]=c0[idx]; g_ctx[idx]=0.f; }
    if (idx < NP*2){ g_pos[idx]=last_pos[idx]; g_cur[idx]=obs[7*NP*2+idx]; }
    if (idx < 128){
        int f = idx>>6, m = idx&63; float s = 0.f;
        for (int e=0;e<32;e++) s += W_sp[f*32+e]*W1[e*64+m];
        g_M[idx]=s;
    }
    if (idx < 64){
        float s = b1[idx];
        for (int e=0;e<32;e++) s += b_sp[e]*W1[e*64+idx];
        g_bc[idx]=s;
    }
}

// ---------------- per-agent kernel: post(t-1) + embed + LSTM(t) + A/B(t) -----------
// 8 agents per block, 256 threads, 64 blocks. t in [0,12]; t==12 does only post(11).
__global__ __launch_bounds__(256)
void k_agent(int t,
             const float* __restrict__ c_in, const float* __restrict__ z,
             const float* __restrict__ eps,
             const float* __restrict__ W_in, const float* __restrict__ b_in,
             const float* __restrict__ W_ih, const float* __restrict__ W_hh,
             const float* __restrict__ b_ih, const float* __restrict__ b_hh,
             const float* __restrict__ W_l2p, const float* __restrict__ b_l2p,
             const float* __restrict__ W1,
             float* __restrict__ out)
{
    __shared__ float sh_hold[8][64];
    __shared__ float sh_ctx[8][64];
    __shared__ float sh_pos[8][2];
    __shared__ float sh_x[8][128];
    __shared__ float sh_hnew[8][64];
    __shared__ float buf[256*33];   // reused: post scratch / emb / W chunks / gates

    const int tid = threadIdx.x;
    const int abase = blockIdx.x*8;

    // load previous h and ctx
    for (int r=0;r<2;r++){
        int idx = r*256+tid; int a = idx>>6, d = idx&63;
        sh_hold[a][d] = g_h[(abase+a)*64+d];
        sh_ctx [a][d] = g_ctx[(abase+a)*64+d];
    }
    __syncthreads();

    if (t > 0){
        int tp = t-1;
        if (tid < 32){
            int a = tid>>2, o = tid&3;    // o: 0=mu0 1=mu1 2=lv0 3=lv1
            int f = o & 1; int lv = o>>1;
            const float* hh = &sh_hold[a][lv?32:0];
            float s = b_l2p[f];
            for (int d=0; d<32; d++) s += hh[d]*W_l2p[d*2+f];
            for (int k=0; k<64; k++) s += sh_ctx[a][k]*W_l2p[(32+k)*2+f];
            int i = abase+a;
            out[(lv?2:1)*(TT*NP*2) + tp*NP*2 + i*2 + f] = s;   // mean / var(logvar)
            buf[a*4+o] = s;
        }
        __syncthreads();
        if (tid < 16){
            int a = tid>>1, f = tid&1; int i = abase+a;
            float mu = buf[a*4+f], lvv = buf[a*4+2+f];
            float p = mu + eps[tp*NP*2 + i*2 + f]*expf(0.5f*lvv);
            out[tp*NP*2 + i*2 + f] = p;                        // pre_pos
            sh_pos[a][f] = p;
            g_pos[i*2+f] = p;
            g_cur[i*2+f] += p;
        }
        __syncthreads();
    } else {
        if (tid < 16){ int a = tid>>1, f = tid&1; sh_pos[a][f] = g_pos[(abase+a)*2+f]; }
        __syncthreads();
    }
    if (t == TT) return;

    // ---- build emb (162 per agent) into buf[a*164+e] ----
    for (int r=0;r<6;r++){
        int idx = r*256+tid;
        if (idx < 8*162){
            int a = idx/162, e = idx%162; float v;
            if (e < 2)        v = sh_pos[a][e];
            else if (e < 66)  v = c_in[(abase+a)*64 + e-2];
            else if (e < 98)  v = z[(abase+a)*32 + e-66];
            else              v = sh_ctx[a][e-98];
            buf[a*164+e] = v;
        }
    }
    __syncthreads();

    // ---- x = relu(emb @ W_in + b_in) : thread owns column u, 4 agents ----
    {
        int u = tid & 127; int a0 = tid >> 7;       // a = a0, a0+2, a0+4, a0+6
        float s0=b_in[u], s1=s0, s2=s0, s3=s0;
        for (int e=0;e<162;e++){
            float w = W_in[e*128+u];
            s0 = fmaf(buf[(a0  )*164+e], w, s0);
            s1 = fmaf(buf[(a0+2)*164+e], w, s1);
            s2 = fmaf(buf[(a0+4)*164+e], w, s2);
            s3 = fmaf(buf[(a0+6)*164+e], w, s3);
        }
        sh_x[a0  ][u] = fmaxf(s0,0.f);
        sh_x[a0+2][u] = fmaxf(s1,0.f);
        sh_x[a0+4][u] = fmaxf(s2,0.f);
        sh_x[a0+6][u] = fmaxf(s3,0.f);
    }
    __syncthreads();

    // ---- gates = x@W_ih^T + h@W_hh^T + b ; thread owns gate unit u4 = tid ----
    float acc[8];
    {
        float binit = b_ih[tid] + b_hh[tid];
        #pragma unroll
        for (int a=0;a<8;a++) acc[a]=binit;
    }
    for (int vc=0; vc<4; vc++){
        for (int r=0;r<32;r++){
            int idx = r*256+tid; int u4 = idx>>5, vv = idx&31;
            buf[u4*33+vv] = W_ih[u4*128 + vc*32 + vv];
        }
        __syncthreads();
        #pragma unroll
        for (int vv=0; vv<32; vv++){
            float wv = buf[tid*33+vv];
            #pragma unroll
            for (int a=0;a<8;a++) acc[a] = fmaf(sh_x[a][vc*32+vv], wv, acc[a]);
        }
        __syncthreads();
    }
    for (int vc=0; vc<2; vc++){
        for (int r=0;r<32;r++){
            int idx = r*256+tid; int u4 = idx>>5, vv = idx&31;
            buf[u4*33+vv] = W_hh[u4*64 + vc*32 + vv];
        }
        __syncthreads();
        #pragma unroll
        for (int vv=0; vv<32; vv++){
            float wv = buf[tid*33+vv];
            #pragma unroll
            for (int a=0;a<8;a++) acc[a] = fmaf(sh_hold[a][vc*32+vv], wv, acc[a]);
        }
        __syncthreads();
    }
    #pragma unroll
    for (int a=0;a<8;a++) buf[a*256+tid] = acc[a];
    __syncthreads();

    // ---- LSTM elementwise ----
    for (int r=0;r<2;r++){
        int idx = r*256+tid; int a = idx>>6, d = idx&63; int i = abase+a;
        float ig = buf[a*256      +d];
        float fg = buf[a*256 +  64+d];
        float gg = buf[a*256 + 128+d];
        float og = buf[a*256 + 192+d];
        float co = g_c[i*64+d];
        float cn = sigmf(fg)*co + sigmf(ig)*tanhf(gg);
        float hn = sigmf(og)*tanhf(cn);
        g_c[i*64+d] = cn;
        g_h[i*64+d] = hn;
        sh_hnew[a][d] = hn;
    }
    __syncthreads();

    // ---- A[j]=h@W1[32:96], B[i]=h@W1[96:160]+bc ----
    {
        int m = tid & 63; int w = (tid>>6)&1; int ah = tid>>7;  // a = ah,ah+2,ah+4,ah+6
        float s0 = w ? g_bc[m] : 0.f; float s1=s0, s2=s0, s3=s0;
        const float* Wp = W1 + (32 + w*64)*64 + m;
        for (int d=0; d<64; d++){
            float wv = Wp[d*64];
            s0 = fmaf(sh_hnew[ah  ][d], wv, s0);
            s1 = fmaf(sh_hnew[ah+2][d], wv, s1);
            s2 = fmaf(sh_hnew[ah+4][d], wv, s2);
            s3 = fmaf(sh_hnew[ah+6][d], wv, s3);
        }
        float* dst = w ? g_B : g_A;
        dst[(abase+ah  )*64+m] = s0;
        dst[(abase+ah+2)*64+m] = s1;
        dst[(abase+ah+4)*64+m] = s2;
        dst[(abase+ah+6)*64+m] = s3;
    }
}

// ---------------- pooling kernel: ctx[i,k] = max_{j valid} relu(h1_ij @ W2 + b2) ----
// 256 blocks (2 i's each), 128 threads. Tile TJ=32 j's -> 64 pairs; register tile 8x4.
__global__ __launch_bounds__(128)
void k_pool(int t, const int* __restrict__ nei,
            const float* __restrict__ W2, const float* __restrict__ b2)
{
    __shared__ float sh_h1[64*68];     // [m][p], pad 68 for STS/alignment
    __shared__ float sh_W2[64*64];     // [m][k]
    __shared__ float sh_curj[64];      // 32 j * 2
    __shared__ int   sh_mask[64];      // [ii*32 + jl]
    __shared__ float sh_red[4*2*64];   // [jg][ii][k]

    const int tid = threadIdx.x;
    const int i0 = blockIdx.x*2;

    for (int r=0;r<32;r++) sh_W2[r*128+tid] = W2[r*128+tid];

    const int mm = tid & 63;
    const float M0 = g_M[mm], M1 = g_M[64+mm];
    const float B0 = g_B[i0*64+mm], B1 = g_B[(i0+1)*64+mm];
    const float ci0x = g_cur[i0*2],   ci0y = g_cur[i0*2+1];
    const float ci1x = g_cur[i0*2+2], ci1y = g_cur[i0*2+3];

    const int kq = tid & 15, jg = (tid>>4)&3, ii = tid>>6;
    float b2r[4];
    #pragma unroll
    for (int kk=0;kk<4;kk++) b2r[kk] = b2[kq*4+kk];

    float cacc[4] = {0.f,0.f,0.f,0.f};
    const int* neib = nei + (long)t*NP*NP + i0*NP;

    for (int jt=0; jt<16; jt++){
        const int jbase = jt*32;
        __syncthreads();                         // protect sh_h1/sh_mask reuse
        if (tid < 64){
            sh_curj[tid] = g_cur[jbase*2 + tid];
            sh_mask[tid] = neib[(tid>>5)*NP + jbase + (tid&31)];
        }
        __syncthreads();

        // stage 1: h1 for 64 pairs x 64 m
        {
            const int ph = tid>>6;   // p parity
            #pragma unroll 4
            for (int r=0;r<32;r++){
                int p  = r*2 + ph;
                int jl = p & 31; int is = p>>5;
                float dx = (is? ci1x:ci0x) - sh_curj[jl*2];
                float dy = (is? ci1y:ci0y) - sh_curj[jl*2+1];
                float v  = g_A[(jbase+jl)*64 + mm] + (is? B1:B0);
                v = fmaf(dx, M0, fmaf(dy, M1, v));
                sh_h1[mm*68 + p] = fmaxf(v, 0.f);
            }
        }
        __syncthreads();

        // stage 2: h2 = h1 @ W2 (8 jj x 4 k per thread), masked max epilogue
        float acc[8][4];
        #pragma unroll
        for (int jj=0;jj<8;jj++){
            #pragma unroll
            for (int kk=0;kk<4;kk++) acc[jj][kk]=0.f;
        }
        #pragma unroll 16
        for (int m=0;m<64;m++){
            const float4 w = *(const float4*)(sh_W2 + m*64 + kq*4);
            const float* hp = sh_h1 + m*68 + (ii<<5) + (jg<<3);
            float4 ha = *(const float4*)(hp);
            float4 hb = *(const float4*)(hp+4);
            float hv[8] = {ha.x,ha.y,ha.z,ha.w,hb.x,hb.y,hb.z,hb.w};
            #pragma unroll
            for (int jj=0;jj<8;jj++){
                acc[jj][0] = fmaf(hv[jj], w.x, acc[jj][0]);
                acc[jj][1] = fmaf(hv[jj], w.y, acc[jj][1]);
                acc[jj][2] = fmaf(hv[jj], w.z, acc[jj][2]);
                acc[jj][3] = fmaf(hv[jj], w.w, acc[jj][3]);
            }
        }
        #pragma unroll
        for (int jj=0;jj<8;jj++){
            if (sh_mask[ii*32 + jg*8 + jj]){
                #pragma unroll
                for (int kk=0;kk<4;kk++)
                    cacc[kk] = fmaxf(cacc[kk], acc[jj][kk] + b2r[kk]);
            }
        }
    }

    __syncthreads();
    #pragma unroll
    for (int kk=0;kk<4;kk++) sh_red[(jg*2+ii)*64 + kq*4+kk] = cacc[kk];
    __syncthreads();
    if (jg == 0){
        #pragma unroll
        for (int kk=0;kk<4;kk++){
            float v = sh_red[(0*2+ii)*64 + kq*4+kk];
            v = fmaxf(v, sh_red[(1*2+ii)*64 + kq*4+kk]);
            v = fmaxf(v, sh_red[(2*2+ii)*64 + kq*4+kk]);
            v = fmaxf(v, sh_red[(3*2+ii)*64 + kq*4+kk]);
            g_ctx[(i0+ii)*64 + kq*4+kk] = v;
        }
    }
}

// ---------------- launch ------------------------------------------------------------
extern "C" void kernel_launch(void* const* d_in, const int* in_sizes, int n_in,
                              void* d_out, int out_size)
{
    const float* last_pos = (const float*)d_in[0];
    const float* c_in     = (const float*)d_in[1];
    const float* z        = (const float*)d_in[2];
    const float* obs      = (const float*)d_in[3];
    const int*   nei      = (const int*)  d_in[4];
    // d_in[5] nei_num_index: unused by reference
    const float* h0       = (const float*)d_in[6];
    const float* c0       = (const float*)d_in[7];
    const float* eps      = (const float*)d_in[8];
    const float* W_in     = (const float*)d_in[9];
    const float* b_in     = (const float*)d_in[10];
    const float* W_ih     = (const float*)d_in[11];
    const float* W_hh     = (const float*)d_in[12];
    const float* b_ih     = (const float*)d_in[13];
    const float* b_hh     = (const float*)d_in[14];
    const float* W_l2p    = (const float*)d_in[15];
    const float* b_l2p    = (const float*)d_in[16];
    const float* W_sp     = (const float*)d_in[17];
    const float* b_sp     = (const float*)d_in[18];
    const float* W1       = (const float*)d_in[19];
    const float* b1       = (const float*)d_in[20];
    const float* W2       = (const float*)d_in[21];
    const float* b2       = (const float*)d_in[22];
    float* out = (float*)d_out;

    k_init<<<128, 256>>>(last_pos, obs, h0, c0, W_sp, b_sp, W1, b1);

    for (int t=0; t<TT; t++){
        k_agent<<<64, 256>>>(t, c_in, z, eps, W_in, b_in, W_ih, W_hh,
                             b_ih, b_hh, W_l2p, b_l2p, W1, out);
        k_pool<<<256, 128>>>(t, nei, W2, b2);
    }
    // final post (outputs for t = 11)
    k_agent<<<64, 256>>>(TT, c_in, z, eps, W_in, b_in, W_ih, W_hh,
                         b_ih, b_hh, W_l2p, b_l2p, W1, out);
}

// round 2
// speedup vs baseline: 1.5390x; 1.5390x over previous
#include <cuda_runtime.h>
#include <math.h>

#define NP 512
#define TT 12

// ---------------- persistent state (device globals; re-initialized every launch) ----
__device__ float g_h[NP*64];
__device__ float g_c[NP*64];
__device__ float g_ctx[NP*64];
__device__ float g_pos[NP*2];
__device__ float g_cur[NP*2];
__device__ float g_A[NP*64];
__device__ float g_B[NP*64];
__device__ float g_M[2*64];
__device__ float g_bc[64];
__device__ float g_xc[NP*128];   // precomputed b_in + [c,z] @ W_in[2:98]

__device__ __forceinline__ float sigmf(float x){ return 1.0f/(1.0f + expf(-x)); }

// ---------------- init: copy initial state, zero ctx, fold W_sp/b_sp/b1 into M/bc ----
__global__ void k_init(const float* __restrict__ last_pos, const float* __restrict__ obs,
                       const float* __restrict__ h0, const float* __restrict__ c0,
                       const float* __restrict__ W_sp, const float* __restrict__ b_sp,
                       const float* __restrict__ W1, const float* __restrict__ b1)
{
    int idx = blockIdx.x*blockDim.x + threadIdx.x;
    if (idx < NP*64){ g_h[idx]=h0[idx]; g_c[idx]=c0[idx]; g_ctx[idx]=0.f; }
    if (idx < NP*2){ g_pos[idx]=last_pos[idx]; g_cur[idx]=obs[7*NP*2+idx]; }
    if (idx < 128){
        int f = idx>>6, m = idx&63; float s = 0.f;
        #pragma unroll 8
        for (int e=0;e<32;e++) s += W_sp[f*32+e]*W1[e*64+m];
        g_M[idx]=s;
    }
    if (idx < 64){
        float s = b1[idx];
        #pragma unroll 8
        for (int e=0;e<32;e++) s += b_sp[e]*W1[e*64+idx];
        g_bc[idx]=s;
    }
}

// ---------------- x_const precompute: 128 blocks x 128 threads, 4 agents/block ------
__global__ __launch_bounds__(128)
void k_xc(const float* __restrict__ c_in, const float* __restrict__ z,
          const float* __restrict__ W_in, const float* __restrict__ b_in)
{
    __shared__ float sh[4][96];
    const int tid = threadIdx.x;
    const int abase = blockIdx.x*4;
    #pragma unroll
    for (int r=0;r<3;r++){
        int idx = r*128+tid; int a = idx/96, e = idx%96;
        sh[a][e] = (e < 64) ? c_in[(abase+a)*64 + e] : z[(abase+a)*32 + e-64];
    }
    __syncthreads();
    float s0=b_in[tid], s1=s0, s2=s0, s3=s0;
    #pragma unroll 8
    for (int e=0;e<96;e++){
        float w = W_in[(2+e)*128 + tid];
        s0 = fmaf(sh[0][e], w, s0);
        s1 = fmaf(sh[1][e], w, s1);
        s2 = fmaf(sh[2][e], w, s2);
        s3 = fmaf(sh[3][e], w, s3);
    }
    g_xc[(abase+0)*128+tid]=s0;
    g_xc[(abase+1)*128+tid]=s1;
    g_xc[(abase+2)*128+tid]=s2;
    g_xc[(abase+3)*128+tid]=s3;
}

// ---------------- per-agent kernel: post(t-1) + embed + LSTM(t) + A/B(t) -----------
// 4 agents per block, 256 threads, 128 blocks. t in [0,12]; t==12 does only post(11).
__global__ __launch_bounds__(256)
void k_agent(int t,
             const float* __restrict__ eps,
             const float* __restrict__ W_in,
             const float* __restrict__ W_ih, const float* __restrict__ W_hh,
             const float* __restrict__ b_ih, const float* __restrict__ b_hh,
             const float* __restrict__ W_l2p, const float* __restrict__ b_l2p,
             const float* __restrict__ W1,
             float* __restrict__ out)
{
    __shared__ float sh_hold[4][64];
    __shared__ float sh_ctx[4][64];
    __shared__ float sh_pos[4][2];
    __shared__ float sh_x[4][128];
    __shared__ float sh_hnew[4][64];
    __shared__ float buf[256*33];   // reused: post scratch / W chunks / gates

    const int tid = threadIdx.x;
    const int abase = blockIdx.x*4;

    // load previous h and ctx (256 threads, 1 element each)
    {
        int a = tid>>6, d = tid&63;
        sh_hold[a][d] = g_h[(abase+a)*64+d];
        sh_ctx [a][d] = g_ctx[(abase+a)*64+d];
    }
    __syncthreads();

    if (t > 0){
        int tp = t-1;
        if (tid < 16){
            int a = tid>>2, o = tid&3;    // o: 0=mu0 1=mu1 2=lv0 3=lv1
            int f = o & 1; int lv = o>>1;
            const float* hh = &sh_hold[a][lv?32:0];
            float s = b_l2p[f];
            #pragma unroll 8
            for (int d=0; d<32; d++) s = fmaf(hh[d], W_l2p[d*2+f], s);
            #pragma unroll 8
            for (int k=0; k<64; k++) s = fmaf(sh_ctx[a][k], W_l2p[(32+k)*2+f], s);
            int i = abase+a;
            out[(lv?2:1)*(TT*NP*2) + tp*NP*2 + i*2 + f] = s;   // mean / var(logvar)
            buf[a*4+o] = s;
        }
        __syncthreads();
        if (tid < 8){
            int a = tid>>1, f = tid&1; int i = abase+a;
            float mu = buf[a*4+f], lvv = buf[a*4+2+f];
            float p = mu + eps[tp*NP*2 + i*2 + f]*expf(0.5f*lvv);
            out[tp*NP*2 + i*2 + f] = p;                        // pre_pos
            sh_pos[a][f] = p;
            g_pos[i*2+f] = p;
            g_cur[i*2+f] += p;
        }
        __syncthreads();
    } else {
        if (tid < 8){ int a = tid>>1, f = tid&1; sh_pos[a][f] = g_pos[(abase+a)*2+f]; }
        __syncthreads();
    }
    if (t == TT) return;

    // ---- x = relu(x_const + pos@W_in[0:2] + ctx@W_in[98:162]) ----
    {
        int u = tid & 127; int a0 = tid >> 7;       // agents a0, a0+2
        float s0 = g_xc[(abase+a0  )*128+u];
        float s1 = g_xc[(abase+a0+2)*128+u];
        float w0 = W_in[u], w1 = W_in[128+u];
        s0 = fmaf(sh_pos[a0  ][0], w0, fmaf(sh_pos[a0  ][1], w1, s0));
        s1 = fmaf(sh_pos[a0+2][0], w0, fmaf(sh_pos[a0+2][1], w1, s1));
        #pragma unroll 8
        for (int k=0;k<64;k++){
            float w = W_in[(98+k)*128+u];
            s0 = fmaf(sh_ctx[a0  ][k], w, s0);
            s1 = fmaf(sh_ctx[a0+2][k], w, s1);
        }
        sh_x[a0  ][u] = fmaxf(s0,0.f);
        sh_x[a0+2][u] = fmaxf(s1,0.f);
    }
    __syncthreads();

    // ---- gates = x@W_ih^T + h@W_hh^T + b ; thread owns gate unit u4 = tid ----
    float acc[4];
    {
        float binit = b_ih[tid] + b_hh[tid];
        #pragma unroll
        for (int a=0;a<4;a++) acc[a]=binit;
    }
    #pragma unroll
    for (int vc=0; vc<4; vc++){
        #pragma unroll 8
        for (int r=0;r<32;r++){
            int idx = r*256+tid; int u4 = idx>>5, vv = idx&31;
            buf[u4*33+vv] = W_ih[u4*128 + vc*32 + vv];
        }
        __syncthreads();
        #pragma unroll
        for (int vv=0; vv<32; vv++){
            float wv = buf[tid*33+vv];
            #pragma unroll
            for (int a=0;a<4;a++) acc[a] = fmaf(sh_x[a][vc*32+vv], wv, acc[a]);
        }
        __syncthreads();
    }
    #pragma unroll
    for (int vc=0; vc<2; vc++){
        #pragma unroll 8
        for (int r=0;r<32;r++){
            int idx = r*256+tid; int u4 = idx>>5, vv = idx&31;
            buf[u4*33+vv] = W_hh[u4*64 + vc*32 + vv];
        }
        __syncthreads();
        #pragma unroll
        for (int vv=0; vv<32; vv++){
            float wv = buf[tid*33+vv];
            #pragma unroll
            for (int a=0;a<4;a++) acc[a] = fmaf(sh_hold[a][vc*32+vv], wv, acc[a]);
        }
        __syncthreads();
    }
    #pragma unroll
    for (int a=0;a<4;a++) buf[a*256+tid] = acc[a];
    __syncthreads();

    // ---- LSTM elementwise (256 threads = 4 agents x 64 dims) ----
    {
        int a = tid>>6, d = tid&63; int i = abase+a;
        float ig = buf[a*256      +d];
        float fg = buf[a*256 +  64+d];
        float gg = buf[a*256 + 128+d];
        float og = buf[a*256 + 192+d];
        float co = g_c[i*64+d];
        float cn = sigmf(fg)*co + sigmf(ig)*tanhf(gg);
        float hn = sigmf(og)*tanhf(cn);
        g_c[i*64+d] = cn;
        g_h[i*64+d] = hn;
        sh_hnew[a][d] = hn;
    }
    __syncthreads();

    // ---- A[j]=h@W1[32:96], B[i]=h@W1[96:160]+bc ----
    {
        int m = tid & 63; int w = (tid>>6)&1; int ah = tid>>7;  // agents ah, ah+2
        float s0 = w ? g_bc[m] : 0.f; float s1 = s0;
        const float* Wp = W1 + (32 + w*64)*64 + m;
        #pragma unroll 8
        for (int d=0; d<64; d++){
            float wv = Wp[d*64];
            s0 = fmaf(sh_hnew[ah  ][d], wv, s0);
            s1 = fmaf(sh_hnew[ah+2][d], wv, s1);
        }
        float* dst = w ? g_B : g_A;
        dst[(abase+ah  )*64+m] = s0;
        dst[(abase+ah+2)*64+m] = s1;
    }
}

// ---------------- pooling kernel with mask compaction -------------------------------
// 512 blocks (1 i each), 128 threads. Compact valid j, then tiles of 64 compacted j.
__global__ __launch_bounds__(128)
void k_pool(int t, const int* __restrict__ nei,
            const float* __restrict__ W2, const float* __restrict__ b2)
{
    __shared__ float sh_h1[64*68];     // [m][p], pad 68
    __shared__ float sh_W2[64*64];     // [m][k]
    __shared__ float sh_curj[128];     // 64 j * 2
    __shared__ int   sh_jidx[NP];
    __shared__ int   sh_cnt;
    __shared__ float sh_red[8*64];     // [jg][k]

    const int tid = threadIdx.x;
    const int i = blockIdx.x;

    if (tid == 0) sh_cnt = 0;
    #pragma unroll 8
    for (int r=0;r<32;r++) sh_W2[r*128+tid] = W2[r*128+tid];
    __syncthreads();

    // ---- compact valid neighbor indices (order irrelevant: max is commutative) ----
    {
        const int* row = nei + (long)t*NP*NP + (long)i*NP;
        #pragma unroll
        for (int c=0;c<4;c++){
            int j = c*128 + tid;
            int v = row[j] > 0;
            unsigned bal = __ballot_sync(0xFFFFFFFFu, v);
            int lane = tid & 31;
            int base = 0;
            if (lane == 0) base = atomicAdd(&sh_cnt, __popc(bal));
            base = __shfl_sync(0xFFFFFFFFu, base, 0);
            if (v) sh_jidx[base + __popc(bal & ((1u<<lane)-1u))] = j;
        }
    }
    __syncthreads();
    const int cnt = sh_cnt;
    const int ntiles = (cnt + 63) >> 6;

    const int mm = tid & 63, ph = tid >> 6;
    const float M0 = g_M[mm], M1 = g_M[64+mm];
    const float Bi = g_B[i*64+mm];
    const float cix = g_cur[i*2], ciy = g_cur[i*2+1];

    const int kq = tid & 15, jg = tid >> 4;     // 8 j-groups of 8
    float b2r[4];
    #pragma unroll
    for (int kk=0;kk<4;kk++) b2r[kk] = b2[kq*4+kk];
    float cacc[4] = {0.f,0.f,0.f,0.f};

    for (int jt=0; jt<ntiles; jt++){
        __syncthreads();                         // protect sh_h1/sh_curj reuse
        {
            int p = tid>>1, f = tid&1;
            int gp = jt*64 + p;
            int j = sh_jidx[(gp < cnt) ? gp : 0];
            sh_curj[p*2+f] = g_cur[j*2+f];
        }
        __syncthreads();

        // stage 1: h1 for 64 compacted pairs x 64 m
        #pragma unroll 4
        for (int r=0;r<32;r++){
            int p = r*2 + ph;
            int gp = jt*64 + p;
            int j = sh_jidx[(gp < cnt) ? gp : 0];
            float dx = cix - sh_curj[p*2];
            float dy = ciy - sh_curj[p*2+1];
            float v  = g_A[j*64 + mm] + Bi;
            v = fmaf(dx, M0, fmaf(dy, M1, v));
            sh_h1[mm*68 + p] = fmaxf(v, 0.f);
        }
        __syncthreads();

        // stage 2: h2 = h1 @ W2 (8 jj x 4 k per thread), masked max epilogue
        float acc[8][4];
        #pragma unroll
        for (int jj=0;jj<8;jj++){
            #pragma unroll
            for (int kk=0;kk<4;kk++) acc[jj][kk]=0.f;
        }
        #pragma unroll 16
        for (int m=0;m<64;m++){
            const float4 w = *(const float4*)(sh_W2 + m*64 + kq*4);
            const float* hp = sh_h1 + m*68 + (jg<<3);
            float4 ha = *(const float4*)(hp);
            float4 hb = *(const float4*)(hp+4);
            float hv[8] = {ha.x,ha.y,ha.z,ha.w,hb.x,hb.y,hb.z,hb.w};
            #pragma unroll
            for (int jj=0;jj<8;jj++){
                acc[jj][0] = fmaf(hv[jj], w.x, acc[jj][0]);
                acc[jj][1] = fmaf(hv[jj], w.y, acc[jj][1]);
                acc[jj][2] = fmaf(hv[jj], w.z, acc[jj][2]);
                acc[jj][3] = fmaf(hv[jj], w.w, acc[jj][3]);
            }
        }
        #pragma unroll
        for (int jj=0;jj<8;jj++){
            int gp = jt*64 + jg*8 + jj;
            if (gp < cnt){
                #pragma unroll
                for (int kk=0;kk<4;kk++)
                    cacc[kk] = fmaxf(cacc[kk], acc[jj][kk] + b2r[kk]);
            }
        }
    }

    __syncthreads();
    #pragma unroll
    for (int kk=0;kk<4;kk++) sh_red[jg*64 + kq*4+kk] = cacc[kk];
    __syncthreads();
    if (tid < 64){
        float v = sh_red[tid];
        #pragma unroll
        for (int g=1; g<8; g++) v = fmaxf(v, sh_red[g*64 + tid]);
        g_ctx[i*64 + tid] = v;
    }
}

// ---------------- launch ------------------------------------------------------------
extern "C" void kernel_launch(void* const* d_in, const int* in_sizes, int n_in,
                              void* d_out, int out_size)
{
    const float* last_pos = (const float*)d_in[0];
    const float* c_in     = (const float*)d_in[1];
    const float* z        = (const float*)d_in[2];
    const float* obs      = (const float*)d_in[3];
    const int*   nei      = (const int*)  d_in[4];
    // d_in[5] nei_num_index: unused by reference
    const float* h0       = (const float*)d_in[6];
    const float* c0       = (const float*)d_in[7];
    const float* eps      = (const float*)d_in[8];
    const float* W_in     = (const float*)d_in[9];
    const float* b_in     = (const float*)d_in[10];
    const float* W_ih     = (const float*)d_in[11];
    const float* W_hh     = (const float*)d_in[12];
    const float* b_ih     = (const float*)d_in[13];
    const float* b_hh     = (const float*)d_in[14];
    const float* W_l2p    = (const float*)d_in[15];
    const float* b_l2p    = (const float*)d_in[16];
    const float* W_sp     = (const float*)d_in[17];
    const float* b_sp     = (const float*)d_in[18];
    const float* W1       = (const float*)d_in[19];
    const float* b1       = (const float*)d_in[20];
    const float* W2       = (const float*)d_in[21];
    const float* b2       = (const float*)d_in[22];
    float* out = (float*)d_out;

    k_init<<<128, 256>>>(last_pos, obs, h0, c0, W_sp, b_sp, W1, b1);
    k_xc<<<128, 128>>>(c_in, z, W_in, b_in);

    for (int t=0; t<TT; t++){
        k_agent<<<128, 256>>>(t, eps, W_in, W_ih, W_hh,
                              b_ih, b_hh, W_l2p, b_l2p, W1, out);
        k_pool<<<512, 128>>>(t, nei, W2, b2);
    }
    // final post (outputs for t = 11)
    k_agent<<<128, 256>>>(TT, eps, W_in, W_ih, W_hh,
                          b_ih, b_hh, W_l2p, b_l2p, W1, out);
}